// round 3
// baseline (speedup 1.0000x reference)
#include <cuda_runtime.h>
#include <math.h>

// ---------------------------------------------------------------------------
// N=100000 nodes, E=1600000 edges, D=64.
// Inputs: 0 nf[N,64] 1 ops[N,4] 2 edge_index[2,E] i32
//  3 W1[128,128] 4 b1[128] 5 W2[128,64] 6 b2[64] 7 W3[64,67] 8 b3[67]
//  9 P1[64,32] 10 pb1[32] 11 P2[32] 12 pb2[1]
// Output: [N,68] = concat(gen[0:67], prob) * mask
// ---------------------------------------------------------------------------

#define NMAX 100000
#define EMAX 1600000
typedef unsigned long long u64;

// Scratch (device globals: allocation-free rule)
__device__ float4 g_nsum4[NMAX * 16];   // holds nmean after gather
__device__ int    g_cnt[NMAX];          // degree
__device__ int    g_off[NMAX];          // CSR row offsets
__device__ int    g_cur[NMAX];          // fill cursors
__device__ int    g_adj[2 * EMAX];      // adjacency

__device__ __forceinline__ void unpack2(u64 v, float &lo, float &hi) {
    asm("mov.b64 {%0, %1}, %2;" : "=f"(lo), "=f"(hi) : "l"(v));
}
#define FFMA2(d, a, b) \
    asm("fma.rn.f32x2 %0, %1, %2, %0;" : "+l"(d) : "l"(a), "l"(b))

// ---------------------------------------------------------------------------
__global__ void zero_cnt_kernel(int n) {
    int i = blockIdx.x * blockDim.x + threadIdx.x;
    if (i < n) g_cnt[i] = 0;
}

__global__ void hist_kernel(const int* __restrict__ ei, int twoE) {
    int stride = gridDim.x * blockDim.x;
    for (int i = blockIdx.x * blockDim.x + threadIdx.x; i < twoE; i += stride)
        atomicAdd(&g_cnt[__ldg(ei + i)], 1);
}

// Single-block exclusive scan of g_cnt -> g_off (also copies into g_cur).
__global__ __launch_bounds__(1024) void scan_kernel(int n) {
    __shared__ int wsum[32];
    int t = threadIdx.x;
    int per = (n + 1023) >> 10;
    int start = t * per;
    int s = 0;
    for (int i = 0; i < per; i++) {
        int j = start + i;
        if (j < n) s += g_cnt[j];
    }
    int lane = t & 31, w = t >> 5;
    int v = s;
    #pragma unroll
    for (int o = 1; o < 32; o <<= 1) {
        int u = __shfl_up_sync(0xffffffffu, v, o);
        if (lane >= o) v += u;
    }
    if (lane == 31) wsum[w] = v;
    __syncthreads();
    if (w == 0) {
        int x = wsum[lane];
        #pragma unroll
        for (int o = 1; o < 32; o <<= 1) {
            int u = __shfl_up_sync(0xffffffffu, x, o);
            if (lane >= o) x += u;
        }
        wsum[lane] = x;
    }
    __syncthreads();
    int run = v - s + (w > 0 ? wsum[w - 1] : 0);   // exclusive prefix
    for (int i = 0; i < per; i++) {
        int j = start + i;
        if (j < n) {
            g_off[j] = run;
            g_cur[j] = run;
            run += g_cnt[j];
        }
    }
}

__global__ void fill_kernel(const int* __restrict__ ei, int E) {
    int stride = gridDim.x * blockDim.x;
    for (int e = blockIdx.x * blockDim.x + threadIdx.x; e < E; e += stride) {
        int s = __ldg(ei + e);
        int d = __ldg(ei + E + e);
        int ps = atomicAdd(&g_cur[s], 1);
        g_adj[ps] = d;
        int pd = atomicAdd(&g_cur[d], 1);
        g_adj[pd] = s;
    }
}

// ---------------------------------------------------------------------------
// Gather: one HALF-WARP per node. Lane l16 owns float4 column l16 of the row.
// Accumulates neighbor rows in registers, writes nmean (sum / max(deg,1)).
__global__ __launch_bounds__(256) void gather_kernel(
    const float* __restrict__ nf, int n)
{
    int lane = threadIdx.x & 31;
    int l16 = lane & 15;
    int hsel = lane & 16;                 // 0 or 16 (half selector)
    int gwarp = (blockIdx.x * 256 + threadIdx.x) >> 5;
    int wstride = (gridDim.x * 256) >> 5;

    for (int w = gwarp; w * 2 < n; w += wstride) {
        int node = w * 2 + (hsel >> 4);
        int vnode = min(node, n - 1);
        int off = g_off[vnode];
        int cnt = g_cnt[vnode];
        float4 acc = make_float4(0.f, 0.f, 0.f, 0.f);

        for (int base = 0; base < cnt; base += 16) {
            int m = cnt - base;
            int nidx = 0;
            if (l16 < m) nidx = __ldg(&g_adj[off + base + l16]);
            #pragma unroll
            for (int j = 0; j < 16; j++) {
                int nbr = __shfl_sync(0xffffffffu, nidx, hsel | j);
                if (j < m) {
                    float4 v = __ldg((const float4*)nf + (size_t)nbr * 16 + l16);
                    acc.x += v.x; acc.y += v.y; acc.z += v.z; acc.w += v.w;
                }
            }
        }
        float invd = 1.f / fmaxf((float)cnt, 1.f);
        if (node < n) {
            acc.x *= invd; acc.y *= invd; acc.z *= invd; acc.w *= invd;
            g_nsum4[(size_t)node * 16 + l16] = acc;
        }
    }
}

// ---------------------------------------------------------------------------
// Fused MLP with packed f32x2 FMA. Shared layout (float offsets):
#define OFF_W1   0        // 16384
#define OFF_B1   16384    // 128
#define OFF_W2   16512    // 8192
#define OFF_B2   24704    // 64
#define OFF_W3   24768    // 64*68 = 4352 (padded stride 68, col67=0)
#define OFF_B3   29120    // 68 (padded)
#define OFF_P1   29188    // 2048
#define OFF_PB1  31236    // 32
#define OFF_P2   31268    // 32
#define OFF_PB2  31300    // 1 (pad 4)
#define PWBASE   31304
#define PW_CTX   0
#define PW_H1    1024
#define PW_H2    2048
#define PW_GEN   2560
#define PW_MK    2832
#define PW       2840
#define SMEM_FLOATS (PWBASE + 8 * PW)   // 54024 floats = 216096 B

__global__ __launch_bounds__(256, 1) void mlp_kernel(
    const float* __restrict__ nf, const float* __restrict__ ops,
    const float* __restrict__ W1, const float* __restrict__ b1,
    const float* __restrict__ W2, const float* __restrict__ b2,
    const float* __restrict__ W3, const float* __restrict__ b3,
    const float* __restrict__ P1, const float* __restrict__ pb1,
    const float* __restrict__ P2, const float* __restrict__ pb2,
    float* __restrict__ out, int n)
{
    extern __shared__ float sm[];
    int tid = threadIdx.x;
    int warp = tid >> 5;
    int lane = tid & 31;

    // ---- cooperative weight load ----
    for (int i = tid; i < 16384; i += 256) sm[OFF_W1 + i] = W1[i];
    for (int i = tid; i < 128;   i += 256) sm[OFF_B1 + i] = b1[i];
    for (int i = tid; i < 8192;  i += 256) sm[OFF_W2 + i] = W2[i];
    for (int i = tid; i < 64;    i += 256) sm[OFF_B2 + i] = b2[i];
    for (int i = tid; i < 64 * 68; i += 256) {
        int r = i / 68, c = i % 68;
        sm[OFF_W3 + i] = (c < 67) ? W3[r * 67 + c] : 0.f;
    }
    for (int i = tid; i < 68;   i += 256) sm[OFF_B3 + i] = (i < 67) ? b3[i] : 0.f;
    for (int i = tid; i < 2048; i += 256) sm[OFF_P1 + i] = P1[i];
    for (int i = tid; i < 32;   i += 256) sm[OFF_PB1 + i] = pb1[i];
    for (int i = tid; i < 32;   i += 256) sm[OFF_P2 + i] = P2[i];
    if (tid == 0) sm[OFF_PB2] = pb2[0];
    __syncthreads();

    float* pw   = sm + PWBASE + warp * PW;
    float* sctx = pw + PW_CTX;   // duplicated ctx  [4][256]
    float* sh1  = pw + PW_H1;    // duplicated h1   [4][256]
    float* sh2  = pw + PW_H2;    // duplicated h2   [4][128]
    float* sgen = pw + PW_GEN;   // gen             [4][68]
    float* smk  = pw + PW_MK;    // mask            [4]

    for (int base = blockIdx.x * 32; base < n; base += gridDim.x * 32) {
        int row0 = base + warp * 4;

        // ---- phase 0: ctx (duplicated; nmean precomputed) + mask ----
        #pragma unroll
        for (int r = 0; r < 4; r++) {
            int row = min(row0 + r, n - 1);
            int cnt = g_cnt[row];
            #pragma unroll
            for (int t = 0; t < 2; t++) {
                int idx = lane + 32 * t;
                float a = nf[(size_t)row * 64 + idx];
                float b = ((const float*)g_nsum4)[(size_t)row * 64 + idx];
                *(float2*)&sctx[r * 256 + 2 * idx]       = make_float2(a, a);
                *(float2*)&sctx[r * 256 + 128 + 2 * idx] = make_float2(b, b);
            }
            if (lane == 0) {
                const float* o = ops + (size_t)row * 4;
                float o0 = o[0], o1 = o[1], o2 = o[2], o3 = o[3];
                float m = fmaxf(fmaxf(o0, o1), fmaxf(o2, o3));
                float e0 = expf(o0 - m);
                float s = e0 + expf(o1 - m) + expf(o2 - m) + expf(o3 - m);
                smk[r] = ((e0 / s) > 0.5f && cnt > 0) ? 1.f : 0.f;
            }
        }
        __syncwarp();

        // ---- phase 1: h1 = relu(ctx @ W1 + b1) : 128 out, pairs ----
        {
            u64 acc[2][4];
            #pragma unroll
            for (int i = 0; i < 2; i++) {
                u64 bv = *(const u64*)&sm[OFF_B1 + 2 * lane + 64 * i];
                #pragma unroll
                for (int r = 0; r < 4; r++) acc[i][r] = bv;
            }
            #pragma unroll 4
            for (int k = 0; k < 128; k++) {
                u64 c0 = *(const u64*)&sctx[2 * k];
                u64 c1 = *(const u64*)&sctx[256 + 2 * k];
                u64 c2 = *(const u64*)&sctx[512 + 2 * k];
                u64 c3 = *(const u64*)&sctx[768 + 2 * k];
                u64 w0 = *(const u64*)&sm[OFF_W1 + k * 128 + 2 * lane];
                u64 w1 = *(const u64*)&sm[OFF_W1 + k * 128 + 64 + 2 * lane];
                FFMA2(acc[0][0], w0, c0); FFMA2(acc[0][1], w0, c1);
                FFMA2(acc[0][2], w0, c2); FFMA2(acc[0][3], w0, c3);
                FFMA2(acc[1][0], w1, c0); FFMA2(acc[1][1], w1, c1);
                FFMA2(acc[1][2], w1, c2); FFMA2(acc[1][3], w1, c3);
            }
            #pragma unroll
            for (int i = 0; i < 2; i++)
                #pragma unroll
                for (int r = 0; r < 4; r++) {
                    float lo, hi; unpack2(acc[i][r], lo, hi);
                    lo = fmaxf(lo, 0.f); hi = fmaxf(hi, 0.f);
                    *(float4*)&sh1[r * 256 + 4 * lane + 128 * i] =
                        make_float4(lo, lo, hi, hi);
                }
        }
        __syncwarp();

        // ---- phase 2: h2 = relu(h1 @ W2 + b2) : 64 out, pairs ----
        {
            u64 acc[4];
            u64 bv = *(const u64*)&sm[OFF_B2 + 2 * lane];
            #pragma unroll
            for (int r = 0; r < 4; r++) acc[r] = bv;
            #pragma unroll 4
            for (int k = 0; k < 128; k++) {
                u64 w  = *(const u64*)&sm[OFF_W2 + k * 64 + 2 * lane];
                FFMA2(acc[0], w, *(const u64*)&sh1[2 * k]);
                FFMA2(acc[1], w, *(const u64*)&sh1[256 + 2 * k]);
                FFMA2(acc[2], w, *(const u64*)&sh1[512 + 2 * k]);
                FFMA2(acc[3], w, *(const u64*)&sh1[768 + 2 * k]);
            }
            #pragma unroll
            for (int r = 0; r < 4; r++) {
                float lo, hi; unpack2(acc[r], lo, hi);
                lo = fmaxf(lo, 0.f); hi = fmaxf(hi, 0.f);
                *(float4*)&sh2[r * 128 + 4 * lane] = make_float4(lo, lo, hi, hi);
            }
        }
        __syncwarp();

        // ---- phase 3: gen = h2 @ W3 + b3 : 68 out (pad), pairs ----
        {
            u64 acc[2][4];
            u64 b0 = *(const u64*)&sm[OFF_B3 + 2 * lane];
            u64 b1v = *(const u64*)&sm[OFF_B3 + 64 + 2 * lane];
            #pragma unroll
            for (int r = 0; r < 4; r++) { acc[0][r] = b0; acc[1][r] = b1v; }
            #pragma unroll 4
            for (int k = 0; k < 64; k++) {
                u64 c0 = *(const u64*)&sh2[2 * k];
                u64 c1 = *(const u64*)&sh2[128 + 2 * k];
                u64 c2 = *(const u64*)&sh2[256 + 2 * k];
                u64 c3 = *(const u64*)&sh2[384 + 2 * k];
                u64 w0 = *(const u64*)&sm[OFF_W3 + k * 68 + 2 * lane];
                u64 w1 = *(const u64*)&sm[OFF_W3 + k * 68 + 64 + 2 * lane];
                FFMA2(acc[0][0], w0, c0); FFMA2(acc[0][1], w0, c1);
                FFMA2(acc[0][2], w0, c2); FFMA2(acc[0][3], w0, c3);
                FFMA2(acc[1][0], w1, c0); FFMA2(acc[1][1], w1, c1);
                FFMA2(acc[1][2], w1, c2); FFMA2(acc[1][3], w1, c3);
            }
            #pragma unroll
            for (int r = 0; r < 4; r++) {
                *(u64*)&sgen[r * 68 + 2 * lane] = acc[0][r];
                if (lane < 2)
                    *(u64*)&sgen[r * 68 + 64 + 2 * lane] = acc[1][r];
            }
        }
        __syncwarp();

        // ---- phase 4: prob = sigmoid(relu(feats @ P1 + pb1) @ P2 + pb2) ----
        float prob[4];
        {
            float a[4];
            float bv = sm[OFF_PB1 + lane];
            #pragma unroll
            for (int r = 0; r < 4; r++) a[r] = bv;
            #pragma unroll 4
            for (int k = 0; k < 64; k++) {
                float w = sm[OFF_P1 + k * 32 + lane];
                a[0] = fmaf(w, sgen[3 + k],       a[0]);
                a[1] = fmaf(w, sgen[68 + 3 + k],  a[1]);
                a[2] = fmaf(w, sgen[136 + 3 + k], a[2]);
                a[3] = fmaf(w, sgen[204 + 3 + k], a[3]);
            }
            float p2 = sm[OFF_P2 + lane];
            float pb2v = sm[OFF_PB2];
            #pragma unroll
            for (int r = 0; r < 4; r++) {
                float part = fmaxf(a[r], 0.f) * p2;
                #pragma unroll
                for (int off = 16; off > 0; off >>= 1)
                    part += __shfl_xor_sync(0xffffffffu, part, off);
                prob[r] = 1.f / (1.f + expf(-(part + pb2v)));
            }
        }

        // ---- phase 5: masked vectorized store ----
        #pragma unroll
        for (int r = 0; r < 4; r++) {
            int row = row0 + r;
            if (row >= n || lane >= 17) continue;
            float mk = smk[r];
            float4 v = *(const float4*)&sgen[r * 68 + 4 * lane];
            if (lane == 16) v.w = prob[r];
            v.x *= mk; v.y *= mk; v.z *= mk; v.w *= mk;
            *(float4*)(out + (size_t)row * 68 + 4 * lane) = v;
        }
        __syncwarp();
    }
}

// ---------------------------------------------------------------------------
extern "C" void kernel_launch(void* const* d_in, const int* in_sizes, int n_in,
                              void* d_out, int out_size)
{
    const float* nf  = (const float*)d_in[0];
    const float* ops = (const float*)d_in[1];
    const int*   ei  = (const int*)d_in[2];
    const float* W1  = (const float*)d_in[3];
    const float* b1  = (const float*)d_in[4];
    const float* W2  = (const float*)d_in[5];
    const float* b2  = (const float*)d_in[6];
    const float* W3  = (const float*)d_in[7];
    const float* b3  = (const float*)d_in[8];
    const float* P1  = (const float*)d_in[9];
    const float* pb1 = (const float*)d_in[10];
    const float* P2  = (const float*)d_in[11];
    const float* pb2 = (const float*)d_in[12];
    float* out = (float*)d_out;

    int n = in_sizes[0] / 64;
    int E = in_sizes[2] / 2;

    // 1) CSR build
    zero_cnt_kernel<<<(n + 255) / 256, 256>>>(n);
    hist_kernel<<<1184, 256>>>(ei, 2 * E);
    scan_kernel<<<1, 1024>>>(n);
    fill_kernel<<<1184, 256>>>(ei, E);

    // 2) gather (half-warp per node) -> nmean
    int blocks = (n + 15) / 16;
    gather_kernel<<<blocks, 256>>>(nf, n);

    // 3) fused MLP
    size_t smem = SMEM_FLOATS * sizeof(float);
    cudaFuncSetAttribute(mlp_kernel, cudaFuncAttributeMaxDynamicSharedMemorySize,
                         (int)smem);
    mlp_kernel<<<148, 256, smem>>>(nf, ops, W1, b1, W2, b2, W3, b3,
                                   P1, pb1, P2, pb2, out, n);
}